// round 1
// baseline (speedup 1.0000x reference)
#include <cuda_runtime.h>
#include <cuda_bf16.h>
#include <cstdint>

// Problem sizes
#define B_SZ 1024
#define F_SZ 256
#define D_SZ 64

// Scratch (device globals; no allocation allowed)
__device__ float g_qkv[3 * F_SZ * D_SZ];    // qkv[t][f][d]
__device__ float g_trans[2 * F_SZ * D_SZ];  // trans[t][f][d]
__device__ float g_MT[F_SZ * F_SZ];         // MT[j][i] = cross[i,j]*gate[i,j]

// ---------------- packed f32x2 helpers (SASS FFMA2 path) ----------------
__device__ __forceinline__ unsigned long long pack2(float lo, float hi) {
    unsigned long long r;
    asm("mov.b64 %0, {%1, %2};" : "=l"(r)
        : "r"(__float_as_uint(lo)), "r"(__float_as_uint(hi)));
    return r;
}
__device__ __forceinline__ void fma2(unsigned long long& d,
                                     unsigned long long a,
                                     unsigned long long b) {
    asm("fma.rn.f32x2 %0, %1, %2, %0;" : "+l"(d) : "l"(a), "l"(b));
}
__device__ __forceinline__ float2 unpack2(unsigned long long v) {
    unsigned lo, hi;
    asm("mov.b64 {%0, %1}, %2;" : "=r"(lo), "=r"(hi) : "l"(v));
    return make_float2(__uint_as_float(lo), __uint_as_float(hi));
}

// ---------------- K1: qkv / trans = indicator @ W ----------------
// grid (F, 5), 64 threads. m<3 -> qkv[m] (W_qkv), m>=3 -> trans[m-3] (W_qk)
__global__ void k_qkv(const float* __restrict__ ind,
                      const float* __restrict__ Wqk,
                      const float* __restrict__ Wqkv) {
    int f = blockIdx.x, m = blockIdx.y;
    int e = threadIdx.x;
    __shared__ float indS[D_SZ];
    indS[e] = ind[f * D_SZ + e];
    __syncthreads();
    const float* W = (m < 3) ? (Wqkv + m * D_SZ * D_SZ)
                             : (Wqk + (m - 3) * D_SZ * D_SZ);
    float acc = 0.f;
#pragma unroll
    for (int d = 0; d < D_SZ; d++) acc = fmaf(indS[d], W[d * D_SZ + e], acc);
    float* dst = (m < 3) ? (g_qkv + m * F_SZ * D_SZ)
                         : (g_trans + (m - 3) * F_SZ * D_SZ);
    dst[f * D_SZ + e] = acc;
}

// ---------------- K2: MT[j][i] = cross[i,j] * (logits[i,j] > 0) ----------------
// grid F (over i), 256 threads (8 warps), warp-cooperative dot products.
__global__ void k_gate() {
    int i = blockIdx.x;
    int tid = threadIdx.x, w = tid >> 5, l = tid & 31;
    __shared__ float q1i[D_SZ], t0i[D_SZ];
    if (tid < 64) q1i[tid] = g_qkv[1 * F_SZ * D_SZ + i * D_SZ + tid];
    else if (tid < 128) t0i[tid - 64] = g_trans[0 * F_SZ * D_SZ + i * D_SZ + (tid - 64)];
    __syncthreads();
    const float* q0 = g_qkv;                     // qkv[0]
    const float* t1 = g_trans + F_SZ * D_SZ;     // trans[1]
    for (int jj = 0; jj < 32; jj++) {
        int j = w * 32 + jj;
        float c = q1i[l] * q0[j * D_SZ + l] + q1i[l + 32] * q0[j * D_SZ + l + 32];
        float gl = t0i[l] * t1[j * D_SZ + l] + t0i[l + 32] * t1[j * D_SZ + l + 32];
#pragma unroll
        for (int o = 16; o > 0; o >>= 1) {
            c  += __shfl_xor_sync(0xFFFFFFFFu, c, o);
            gl += __shfl_xor_sync(0xFFFFFFFFu, gl, o);
        }
        if (l == 0) g_MT[j * F_SZ + i] = (gl > 0.f) ? c : 0.f;
    }
}

// ---------------- K3: main per-batch kernel ----------------
// One block per batch b. 256 threads.
//   Phase A: load feature[b] to smem, compute s0,s1,s2 (warp-cooperative).
//   Phase B: P[j][d] = s1[j]*qkv2[j][d] in smem (overwrites feature buffer).
//   Phase C: Out[i,d] = (s0[i]*s2[i]) * sum_j MT[j][i]*P[j][d]
//            thread tile: 8 i-rows x 8 d-cols, accumulators packed f32x2 along i.
#define MCHUNK 16
#define SMEM_FLOATS (F_SZ * D_SZ + MCHUNK * F_SZ + 2 * F_SZ)
#define SMEM_BYTES (SMEM_FLOATS * 4)

__global__ void __launch_bounds__(256, 2)
k_main(const float* __restrict__ feature, float* __restrict__ out) {
    extern __shared__ float sm[];
    float* P   = sm;                          // F*D = 16384 floats
    float* MTs = sm + F_SZ * D_SZ;            // MCHUNK*F = 4096 floats
    float* s1s = MTs + MCHUNK * F_SZ;         // F
    float* sas = s1s + F_SZ;                  // F

    int b = blockIdx.x, tid = threadIdx.x;
    int w = tid >> 5, l = tid & 31;
    const float* fb = feature + (size_t)b * (F_SZ * D_SZ);

    // Phase A: feature[b] -> smem (as fs, stored in P buffer)
    {
        float4* Pv = (float4*)P;
        const float4* fv = (const float4*)fb;
#pragma unroll
        for (int k = 0; k < 16; k++) Pv[tid + k * 256] = fv[tid + k * 256];
    }
    __syncthreads();

    // s_t[i] = fs[i] . qkv[t][i]; warp w handles rows w*32..w*32+31
    for (int jj = 0; jj < 32; jj++) {
        int i = w * 32 + jj;
        float f0 = P[i * D_SZ + l], f1 = P[i * D_SZ + l + 32];
        const float* q = g_qkv + i * D_SZ;
        float a0 = f0 * q[l]                     + f1 * q[l + 32];
        float a1 = f0 * q[F_SZ * D_SZ + l]       + f1 * q[F_SZ * D_SZ + l + 32];
        float a2 = f0 * q[2 * F_SZ * D_SZ + l]   + f1 * q[2 * F_SZ * D_SZ + l + 32];
#pragma unroll
        for (int o = 16; o > 0; o >>= 1) {
            a0 += __shfl_xor_sync(0xFFFFFFFFu, a0, o);
            a1 += __shfl_xor_sync(0xFFFFFFFFu, a1, o);
            a2 += __shfl_xor_sync(0xFFFFFFFFu, a2, o);
        }
        if (l == 0) { s1s[i] = a1; sas[i] = a0 * a2; }
    }
    __syncthreads();

    // Phase B: P[j][d] = s1[j] * qkv2[j][d]  (overwrite fs; fs no longer needed)
    {
        const float4* q2v = (const float4*)(g_qkv + 2 * F_SZ * D_SZ);
        float4* Pv = (float4*)P;
#pragma unroll
        for (int k = 0; k < 16; k++) {
            int idx = tid + k * 256;          // float4 index; j = idx/16
            float s1 = s1s[idx >> 4];
            float4 q = q2v[idx];
            Pv[idx] = make_float4(q.x * s1, q.y * s1, q.z * s1, q.w * s1);
        }
    }
    __syncthreads();

    // Phase C: main GEMM
    int i_base = (tid >> 3) << 3;   // 0..248 step 8 (8-lane broadcast groups)
    int d_base = (tid & 7) << 3;    // 0..56  step 8

    unsigned long long acc[4][8];   // packed pairs along i: rows (i_base+2k, i_base+2k+1)
#pragma unroll
    for (int ii = 0; ii < 4; ii++)
#pragma unroll
        for (int dd = 0; dd < 8; dd++) acc[ii][dd] = 0ull;

    for (int j0 = 0; j0 < F_SZ; j0 += MCHUNK) {
        // stage MT rows j0..j0+MCHUNK into smem (coalesced)
        {
            const float4* src = (const float4*)(g_MT + j0 * F_SZ);
            float4* dst = (float4*)MTs;
#pragma unroll
            for (int k = 0; k < 4; k++) dst[tid + k * 256] = src[tid + k * 256];
        }
        __syncthreads();
#pragma unroll
        for (int jj = 0; jj < MCHUNK; jj++) {
            const float* prow = P + (j0 + jj) * D_SZ + d_base;
            float4 p0 = *(const float4*)prow;
            float4 p1 = *(const float4*)(prow + 4);
            unsigned long long pd[8];
            pd[0] = pack2(p0.x, p0.x); pd[1] = pack2(p0.y, p0.y);
            pd[2] = pack2(p0.z, p0.z); pd[3] = pack2(p0.w, p0.w);
            pd[4] = pack2(p1.x, p1.x); pd[5] = pack2(p1.y, p1.y);
            pd[6] = pack2(p1.z, p1.z); pd[7] = pack2(p1.w, p1.w);
            // M pairs come pre-packed from smem (consecutive floats = one u64)
            const ulonglong2* mrow =
                (const ulonglong2*)(MTs + jj * F_SZ + i_base);
            ulonglong2 mA = mrow[0];
            ulonglong2 mB = mrow[1];
            unsigned long long mm[4] = { mA.x, mA.y, mB.x, mB.y };
#pragma unroll
            for (int ii = 0; ii < 4; ii++)
#pragma unroll
                for (int dd = 0; dd < 8; dd++) fma2(acc[ii][dd], mm[ii], pd[dd]);
        }
        __syncthreads();
    }

    // Epilogue: scale by a[i] = s0*s2 and store
    float* ob = out + (size_t)b * (F_SZ * D_SZ);
#pragma unroll
    for (int ii = 0; ii < 4; ii++) {
        int i0 = i_base + 2 * ii;
        float a0 = sas[i0], a1 = sas[i0 + 1];
        float r0[8], r1[8];
#pragma unroll
        for (int dd = 0; dd < 8; dd++) {
            float2 v = unpack2(acc[ii][dd]);
            r0[dd] = v.x * a0;
            r1[dd] = v.y * a1;
        }
        float* o0 = ob + i0 * D_SZ + d_base;
        float* o1 = o0 + D_SZ;
        *(float4*)o0       = make_float4(r0[0], r0[1], r0[2], r0[3]);
        *(float4*)(o0 + 4) = make_float4(r0[4], r0[5], r0[6], r0[7]);
        *(float4*)o1       = make_float4(r1[0], r1[1], r1[2], r1[3]);
        *(float4*)(o1 + 4) = make_float4(r1[4], r1[5], r1[6], r1[7]);
    }
}

// ---------------- launch ----------------
extern "C" void kernel_launch(void* const* d_in, const int* in_sizes, int n_in,
                              void* d_out, int out_size) {
    const float *feature = nullptr, *indicator = nullptr;
    const float *Wqk = nullptr, *Wqkv = nullptr;
    for (int k = 0; k < n_in; k++) {
        switch (in_sizes[k]) {
            case B_SZ * F_SZ * D_SZ: feature   = (const float*)d_in[k]; break;
            case F_SZ * D_SZ:        indicator = (const float*)d_in[k]; break;
            case 2 * D_SZ * D_SZ:    Wqk       = (const float*)d_in[k]; break;
            case 3 * D_SZ * D_SZ:    Wqkv      = (const float*)d_in[k]; break;
        }
    }
    float* out = (float*)d_out;

    cudaFuncSetAttribute(k_main, cudaFuncAttributeMaxDynamicSharedMemorySize,
                         SMEM_BYTES);

    k_qkv<<<dim3(F_SZ, 5), D_SZ>>>(indicator, Wqk, Wqkv);
    k_gate<<<F_SZ, 256>>>();
    k_main<<<B_SZ, 256, SMEM_BYTES>>>(feature, out);
}

// round 5
// speedup vs baseline: 1.3781x; 1.3781x over previous
#include <cuda_runtime.h>
#include <cuda_bf16.h>
#include <cstdint>

#define B_SZ 1024
#define F_SZ 256
#define D_SZ 64
#define GRID_MAIN 148
#define NUNITS 2048   // 2 halves x 1024 batches

// ---------------- device scratch ----------------
__device__ float g_qkv[3 * F_SZ * D_SZ];     // qkv[t][f][d]
__device__ float g_trans[2 * F_SZ * D_SZ];   // trans[t][f][d]
__device__ float g_S1[B_SZ * F_SZ];          // s1[b][j]
__device__ float g_SA[B_SZ * F_SZ];          // s0*s2 [b][i]
__device__ __nv_bfloat16 g_Mhi[F_SZ * F_SZ]; // gated cross hi
__device__ __nv_bfloat16 g_Mlo[F_SZ * F_SZ]; // gated cross lo

// ---------------- smem layout (bytes) ----------------
#define A_STR 264                             // bf16 per A row (256 + 8 pad)
#define Z_STR 72                              // bf16 per Z row (64 + 8 pad)
#define SM_AHI 0
#define SM_ALO (128 * A_STR * 2)              // 67584
#define SM_ZH  (SM_ALO + 128 * A_STR * 2)     // 135168
#define SM_ZL  (SM_ZH + 256 * Z_STR * 2)      // 172032
#define SMEM_TOTAL (SM_ZL + 256 * Z_STR * 2)  // 208896

// ---------------- helpers ----------------
__device__ __forceinline__ uint32_t smem_u32(const void* p) {
    uint32_t a;
    asm("{ .reg .u64 t; cvta.to.shared.u64 t, %1; cvt.u32.u64 %0, t; }"
        : "=r"(a) : "l"(p));
    return a;
}

#define LDSM4(r, a) \
    asm volatile("ldmatrix.sync.aligned.m8n8.x4.shared.b16 {%0,%1,%2,%3}, [%4];" \
                 : "=r"((r)[0]), "=r"((r)[1]), "=r"((r)[2]), "=r"((r)[3]) : "r"(a))
#define LDSM4T(r, a) \
    asm volatile("ldmatrix.sync.aligned.m8n8.x4.trans.shared.b16 {%0,%1,%2,%3}, [%4];" \
                 : "=r"((r)[0]), "=r"((r)[1]), "=r"((r)[2]), "=r"((r)[3]) : "r"(a))
#define MMA16816(d, a, b0, b1) \
    asm volatile("mma.sync.aligned.m16n8k16.row.col.f32.bf16.bf16.f32 " \
                 "{%0,%1,%2,%3}, {%4,%5,%6,%7}, {%8,%9}, {%0,%1,%2,%3};" \
                 : "+f"((d)[0]), "+f"((d)[1]), "+f"((d)[2]), "+f"((d)[3]) \
                 : "r"((a)[0]), "r"((a)[1]), "r"((a)[2]), "r"((a)[3]), \
                   "r"(b0), "r"(b1))

// ---------------- K1: qkv / trans = indicator @ W ----------------
__global__ void k_qkv(const float* __restrict__ ind,
                      const float* __restrict__ Wqk,
                      const float* __restrict__ Wqkv) {
    int m = blockIdx.y;
    int fl = threadIdx.x >> 6, e = threadIdx.x & 63;
    int f = blockIdx.x * 4 + fl;
    __shared__ float indS[4 * D_SZ];
    indS[threadIdx.x] = ind[f * D_SZ + e];
    __syncthreads();
    const float* W = (m < 3) ? (Wqkv + m * D_SZ * D_SZ)
                             : (Wqk + (m - 3) * D_SZ * D_SZ);
    float acc = 0.f;
#pragma unroll
    for (int d = 0; d < D_SZ; d++) acc = fmaf(indS[fl * 64 + d], W[d * D_SZ + e], acc);
    if (m < 3) g_qkv[m * F_SZ * D_SZ + f * D_SZ + e] = acc;
    else       g_trans[(m - 3) * F_SZ * D_SZ + f * D_SZ + e] = acc;
}

// ---------------- K2: M[i][j] = cross*gate, bf16 hi/lo ----------------
__global__ void k_gate() {
    int i = blockIdx.x;
    int tid = threadIdx.x, w = tid >> 5, l = tid & 31;
    __shared__ float q1i[D_SZ], t0i[D_SZ];
    if (tid < 64) q1i[tid] = g_qkv[F_SZ * D_SZ + i * D_SZ + tid];
    else if (tid < 128) t0i[tid - 64] = g_trans[i * D_SZ + (tid - 64)];
    __syncthreads();
    const float* q0 = g_qkv;
    const float* t1 = g_trans + F_SZ * D_SZ;
    for (int jj = 0; jj < 32; jj++) {
        int j = w * 32 + jj;
        float c  = q1i[l] * q0[j * D_SZ + l] + q1i[l + 32] * q0[j * D_SZ + l + 32];
        float gl = t0i[l] * t1[j * D_SZ + l] + t0i[l + 32] * t1[j * D_SZ + l + 32];
#pragma unroll
        for (int o = 16; o > 0; o >>= 1) {
            c  += __shfl_xor_sync(0xFFFFFFFFu, c, o);
            gl += __shfl_xor_sync(0xFFFFFFFFu, gl, o);
        }
        if (l == 0) {
            float v = (gl > 0.f) ? c : 0.f;
            __nv_bfloat16 hi = __float2bfloat16(v);
            g_Mhi[i * F_SZ + j] = hi;
            g_Mlo[i * F_SZ + j] = __float2bfloat16(v - __bfloat162float(hi));
        }
    }
}

// ---------------- K3: S1/SA from feature (streams feature once) ----------------
__global__ void __launch_bounds__(256) k_s(const float* __restrict__ feature) {
    int w = threadIdx.x >> 5, l = threadIdx.x & 31;
    int b0 = blockIdx.x * 4;
    for (int jj = 0; jj < 32; jj++) {
        int i = w * 32 + jj;
        const float* q = g_qkv + i * D_SZ;
        float q0a = q[l],                   q0b = q[l + 32];
        float q1a = q[F_SZ * D_SZ + l],     q1b = q[F_SZ * D_SZ + l + 32];
        float q2a = q[2 * F_SZ * D_SZ + l], q2b = q[2 * F_SZ * D_SZ + l + 32];
#pragma unroll
        for (int bb = 0; bb < 4; bb++) {
            const float* fp = feature + (size_t)(b0 + bb) * (F_SZ * D_SZ) + i * D_SZ;
            float fa = fp[l], fb = fp[l + 32];
            float d0 = fa * q0a + fb * q0b;
            float d1 = fa * q1a + fb * q1b;
            float d2 = fa * q2a + fb * q2b;
#pragma unroll
            for (int o = 16; o > 0; o >>= 1) {
                d0 += __shfl_xor_sync(0xFFFFFFFFu, d0, o);
                d1 += __shfl_xor_sync(0xFFFFFFFFu, d1, o);
                d2 += __shfl_xor_sync(0xFFFFFFFFu, d2, o);
            }
            if (l == 0) {
                g_S1[(b0 + bb) * F_SZ + i] = d1;
                g_SA[(b0 + bb) * F_SZ + i] = d0 * d2;
            }
        }
    }
}

// ---------------- K4: persistent mma.sync main kernel ----------------
// Unit u = h*1024 + b. CTA c handles [c*2048/148, (c+1)*2048/148).
// Out[i,d] = SA[b,i] * sum_j M[i,j]*Z[b][j,d], 3-term bf16 split.
__global__ void __launch_bounds__(256, 1)
k_main(float* __restrict__ out) {
    extern __shared__ char sm[];
    uint32_t sb = smem_u32(sm);
    int tid = threadIdx.x, w = tid >> 5, lane = tid & 31;
    int c = blockIdx.x;
    int u0 = (c * NUNITS) / GRID_MAIN, u1 = ((c + 1) * NUNITS) / GRID_MAIN;

    int m0 = (w >> 1) * 32;        // warp row block within 128-half
    int n0 = (w & 1) * 32;         // warp col block within 64
    int g = lane >> 2, t4 = lane & 3;

    uint32_t aBase = sb + SM_AHI + (uint32_t)(m0 + (lane & 15)) * (A_STR * 2)
                     + (uint32_t)(lane >> 4) * 16;
    uint32_t bBase = sb + SM_ZH + (uint32_t)(lane & 15) * (Z_STR * 2)
                     + (uint32_t)(n0 + 8 * (lane >> 4)) * 2;

    int curH = -1;
    for (int u = u0; u < u1; u++) {
        int h = u >> 10, b = u & 1023;

        if (h != curH) {
            __syncthreads();
            const uint2* mh = (const uint2*)(g_Mhi + h * 128 * F_SZ);
            const uint2* ml = (const uint2*)(g_Mlo + h * 128 * F_SZ);
            for (int idx = tid; idx < 128 * 64; idx += 256) {
                int r = idx >> 6, c4 = idx & 63;
                *(uint2*)(sm + SM_AHI + r * (A_STR * 2) + c4 * 8) = mh[idx];
                *(uint2*)(sm + SM_ALO + r * (A_STR * 2) + c4 * 8) = ml[idx];
            }
            curH = h;
        }

        __syncthreads();  // protect Z (and A) vs prior readers
        // ---- build Z[j][d] = S1[b,j]*Q2[j,d], bf16 hi/lo ----
        {
            const float* q2 = g_qkv + 2 * F_SZ * D_SZ;
            const float* s1p = g_S1 + b * F_SZ;
            for (int e = tid; e < 256 * 32; e += 256) {
                int j = e >> 5, dp = e & 31;
                float s1 = __ldg(s1p + j);
                float2 q = ((const float2*)(q2 + j * 64))[dp];
                float z0 = q.x * s1, z1 = q.y * s1;
                __nv_bfloat16 h0 = __float2bfloat16(z0);
                __nv_bfloat16 h1 = __float2bfloat16(z1);
                __nv_bfloat16 l0 = __float2bfloat16(z0 - __bfloat162float(h0));
                __nv_bfloat16 l1 = __float2bfloat16(z1 - __bfloat162float(h1));
                uint32_t hp = ((uint32_t)__bfloat16_as_ushort(h1) << 16) |
                              __bfloat16_as_ushort(h0);
                uint32_t lp = ((uint32_t)__bfloat16_as_ushort(l1) << 16) |
                              __bfloat16_as_ushort(l0);
                *(uint32_t*)(sm + SM_ZH + j * (Z_STR * 2) + dp * 4) = hp;
                *(uint32_t*)(sm + SM_ZL + j * (Z_STR * 2) + dp * 4) = lp;
            }
        }
        __syncthreads();

        // ---- mma mainloop: warp tile 32x32, K=256 ----
        float acc[8][4];
#pragma unroll
        for (int i = 0; i < 8; i++)
#pragma unroll
            for (int q = 0; q < 4; q++) acc[i][q] = 0.f;

#pragma unroll 2
        for (int k = 0; k < 16; k++) {
            uint32_t kA = (uint32_t)k * 32;              // 16 bf16 along A row
            uint32_t kB = (uint32_t)k * 16 * (Z_STR * 2); // 16 Z rows
            uint32_t ah0[4], ah1[4], al0[4], al1[4];
            LDSM4(ah0, aBase + kA);
            LDSM4(ah1, aBase + 16 * (A_STR * 2) + kA);
            LDSM4(al0, aBase + (SM_ALO - SM_AHI) + kA);
            LDSM4(al1, aBase + (SM_ALO - SM_AHI) + 16 * (A_STR * 2) + kA);
            uint32_t bh0[4], bh1[4], bl0[4], bl1[4];
            LDSM4T(bh0, bBase + kB);
            LDSM4T(bh1, bBase + kB + 32);
            LDSM4T(bl0, bBase + (SM_ZL - SM_ZH) + kB);
            LDSM4T(bl1, bBase + (SM_ZL - SM_ZH) + kB + 32);

            // mt=0
            MMA16816(acc[0], ah0, bh0[0], bh0[1]);
            MMA16816(acc[1], ah0, bh0[2], bh0[3]);
            MMA16816(acc[2], ah0, bh1[0], bh1[1]);
            MMA16816(acc[3], ah0, bh1[2], bh1[3]);
            MMA16816(acc[0], ah0, bl0[0], bl0[1]);
            MMA16816(acc[1], ah0, bl0[2], bl0[3]);
            MMA16816(acc[2], ah0, bl1[0], bl1[1]);
            MMA16816(acc[3], ah0, bl1[2], bl1[3]);
            MMA16816(acc[0], al0, bh0[0], bh0[1]);
            MMA16816(acc[1], al0, bh0[2], bh0[3]);
            MMA16816(acc[2], al0, bh1[0], bh1[1]);
            MMA16816(acc[3], al0, bh1[2], bh1[3]);
            // mt=1
            MMA16816(acc[4], ah1, bh0[0], bh0[1]);
            MMA16816(acc[5], ah1, bh0[2], bh0[3]);
            MMA16816(acc[6], ah1, bh1[0], bh1[1]);
            MMA16816(acc[7], ah1, bh1[2], bh1[3]);
            MMA16816(acc[4], ah1, bl0[0], bl0[1]);
            MMA16816(acc[5], ah1, bl0[2], bl0[3]);
            MMA16816(acc[6], ah1, bl1[0], bl1[1]);
            MMA16816(acc[7], ah1, bl1[2], bl1[3]);
            MMA16816(acc[4], al1, bh0[0], bh0[1]);
            MMA16816(acc[5], al1, bh0[2], bh0[3]);
            MMA16816(acc[6], al1, bh1[0], bh1[1]);
            MMA16816(acc[7], al1, bh1[2], bh1[3]);
        }

        // ---- epilogue: scale by SA and store ----
        const float* sap = g_SA + b * F_SZ + h * 128;
        float* ob = out + (size_t)b * (F_SZ * D_SZ) + h * 128 * D_SZ;
#pragma unroll
        for (int mt = 0; mt < 2; mt++) {
            int r0 = m0 + mt * 16 + g;
            float sa0 = __ldg(sap + r0), sa1 = __ldg(sap + r0 + 8);
#pragma unroll
            for (int pt = 0; pt < 4; pt++) {   // 4 n-subtiles of 8
                float* a = acc[mt * 4 + pt];
                int col = n0 + pt * 8 + 2 * t4;
                float2 v0 = make_float2(a[0] * sa0, a[1] * sa0);
                float2 v1 = make_float2(a[2] * sa1, a[3] * sa1);
                *(float2*)(ob + r0 * 64 + col) = v0;
                *(float2*)(ob + (r0 + 8) * 64 + col) = v1;
            }
        }
    }
}

// ---------------- launch ----------------
extern "C" void kernel_launch(void* const* d_in, const int* in_sizes, int n_in,
                              void* d_out, int out_size) {
    const float *feature = nullptr, *indicator = nullptr;
    const float *Wqk = nullptr, *Wqkv = nullptr;
    for (int k = 0; k < n_in; k++) {
        switch (in_sizes[k]) {
            case B_SZ * F_SZ * D_SZ: feature   = (const float*)d_in[k]; break;
            case F_SZ * D_SZ:        indicator = (const float*)d_in[k]; break;
            case 2 * D_SZ * D_SZ:    Wqk       = (const float*)d_in[k]; break;
            case 3 * D_SZ * D_SZ:    Wqkv      = (const float*)d_in[k]; break;
        }
    }
    float* out = (float*)d_out;

    cudaFuncSetAttribute(k_main, cudaFuncAttributeMaxDynamicSharedMemorySize,
                         SMEM_TOTAL);

    k_qkv<<<dim3(64, 5), 256>>>(indicator, Wqk, Wqkv);
    k_gate<<<F_SZ, 256>>>();
    k_s<<<256, 256>>>(feature);
    k_main<<<GRID_MAIN, 256, SMEM_TOTAL>>>(out);
}

// round 6
// speedup vs baseline: 1.4534x; 1.0547x over previous
#include <cuda_runtime.h>
#include <cuda_bf16.h>
#include <cstdint>

#define B_SZ 1024
#define F_SZ 256
#define D_SZ 64
#define GRID_MAIN 148
#define NUNITS 2048   // 2 halves x 1024 batches

// ---------------- device scratch ----------------
__device__ float g_qkv[3 * F_SZ * D_SZ];     // qkv[t][f][d]
__device__ float g_trans[2 * F_SZ * D_SZ];   // trans[t][f][d]
__device__ float g_S1[B_SZ * F_SZ];          // s1[b][j]
__device__ float g_SA[B_SZ * F_SZ];          // s0*s2 [b][i]
__device__ __nv_bfloat16 g_Mhi[F_SZ * F_SZ]; // gated cross hi
__device__ __nv_bfloat16 g_Mlo[F_SZ * F_SZ]; // gated cross lo

// ---------------- smem layout (bytes) ----------------
#define A_STR 264                             // bf16 per A row (256 + 8 pad)
#define Z_STR 72                              // bf16 per Z row (64 + 8 pad)
#define SM_AHI 0
#define SM_ALO (128 * A_STR * 2)              // 67584
#define SM_ZH  (SM_ALO + 128 * A_STR * 2)     // 135168
#define SM_ZL  (SM_ZH + 256 * Z_STR * 2)      // 172032 (also reused as staging)
#define SMEM_TOTAL (SM_ZL + 256 * Z_STR * 2)  // 208896

// ---------------- helpers ----------------
__device__ __forceinline__ uint32_t smem_u32(const void* p) {
    uint32_t a;
    asm("{ .reg .u64 t; cvta.to.shared.u64 t, %1; cvt.u32.u64 %0, t; }"
        : "=r"(a) : "l"(p));
    return a;
}

#define LDSM4(r, a) \
    asm volatile("ldmatrix.sync.aligned.m8n8.x4.shared.b16 {%0,%1,%2,%3}, [%4];" \
                 : "=r"((r)[0]), "=r"((r)[1]), "=r"((r)[2]), "=r"((r)[3]) : "r"(a))
#define LDSM4T(r, a) \
    asm volatile("ldmatrix.sync.aligned.m8n8.x4.trans.shared.b16 {%0,%1,%2,%3}, [%4];" \
                 : "=r"((r)[0]), "=r"((r)[1]), "=r"((r)[2]), "=r"((r)[3]) : "r"(a))
#define MMA16816(d, a, b0, b1) \
    asm volatile("mma.sync.aligned.m16n8k16.row.col.f32.bf16.bf16.f32 " \
                 "{%0,%1,%2,%3}, {%4,%5,%6,%7}, {%8,%9}, {%0,%1,%2,%3};" \
                 : "+f"((d)[0]), "+f"((d)[1]), "+f"((d)[2]), "+f"((d)[3]) \
                 : "r"((a)[0]), "r"((a)[1]), "r"((a)[2]), "r"((a)[3]), \
                   "r"(b0), "r"(b1))

// ---------------- K1: qkv / trans = indicator @ W ----------------
__global__ void k_qkv(const float* __restrict__ ind,
                      const float* __restrict__ Wqk,
                      const float* __restrict__ Wqkv) {
    int m = blockIdx.y;
    int fl = threadIdx.x >> 6, e = threadIdx.x & 63;
    int f = blockIdx.x * 4 + fl;
    __shared__ float indS[4 * D_SZ];
    indS[threadIdx.x] = ind[f * D_SZ + e];
    __syncthreads();
    const float* W = (m < 3) ? (Wqkv + m * D_SZ * D_SZ)
                             : (Wqk + (m - 3) * D_SZ * D_SZ);
    float acc = 0.f;
#pragma unroll
    for (int d = 0; d < D_SZ; d++) acc = fmaf(indS[fl * 64 + d], W[d * D_SZ + e], acc);
    if (m < 3) g_qkv[m * F_SZ * D_SZ + f * D_SZ + e] = acc;
    else       g_trans[(m - 3) * F_SZ * D_SZ + f * D_SZ + e] = acc;
}

// ---------------- K2: merged gate + s kernel ----------------
// blocks [0,256): gate rows; blocks [256,512): S1/SA for 4 batches each.
__global__ void __launch_bounds__(256) k_prep(const float* __restrict__ feature) {
    int tid = threadIdx.x, w = tid >> 5, l = tid & 31;
    if (blockIdx.x < 256) {
        // ---- gate: M[i][j] = cross * (logits>0), bf16 hi/lo ----
        int i = blockIdx.x;
        __shared__ float q1i[D_SZ], t0i[D_SZ];
        if (tid < 64) q1i[tid] = g_qkv[F_SZ * D_SZ + i * D_SZ + tid];
        else if (tid < 128) t0i[tid - 64] = g_trans[i * D_SZ + (tid - 64)];
        __syncthreads();
        const float* q0 = g_qkv;
        const float* t1 = g_trans + F_SZ * D_SZ;
        for (int jj = 0; jj < 32; jj++) {
            int j = w * 32 + jj;
            float c  = q1i[l] * q0[j * D_SZ + l] + q1i[l + 32] * q0[j * D_SZ + l + 32];
            float gl = t0i[l] * t1[j * D_SZ + l] + t0i[l + 32] * t1[j * D_SZ + l + 32];
#pragma unroll
            for (int o = 16; o > 0; o >>= 1) {
                c  += __shfl_xor_sync(0xFFFFFFFFu, c, o);
                gl += __shfl_xor_sync(0xFFFFFFFFu, gl, o);
            }
            if (l == 0) {
                float v = (gl > 0.f) ? c : 0.f;
                __nv_bfloat16 hi = __float2bfloat16(v);
                g_Mhi[i * F_SZ + j] = hi;
                g_Mlo[i * F_SZ + j] = __float2bfloat16(v - __bfloat162float(hi));
            }
        }
    } else {
        // ---- s: S1[b,i] = f.q1, SA[b,i] = (f.q0)*(f.q2) ----
        // block handles 4 batches; half-warps process two batches in parallel.
        int b0 = (blockIdx.x - 256) * 4;
        int hb = l >> 4, ll = l & 15;
        for (int ii = 0; ii < 32; ii++) {
            int i = w * 32 + ii;
            const float4* qp = (const float4*)(g_qkv + i * D_SZ) + ll;
            float4 q0 = qp[0];
            float4 q1 = qp[(F_SZ * D_SZ) / 4];
            float4 q2 = qp[(2 * F_SZ * D_SZ) / 4];
#pragma unroll
            for (int bp = 0; bp < 2; bp++) {
                int b = b0 + bp * 2 + hb;
                float4 f = *((const float4*)(feature + (size_t)b * (F_SZ * D_SZ)
                                             + i * D_SZ) + ll);
                float d0 = f.x * q0.x + f.y * q0.y + f.z * q0.z + f.w * q0.w;
                float d1 = f.x * q1.x + f.y * q1.y + f.z * q1.z + f.w * q1.w;
                float d2 = f.x * q2.x + f.y * q2.y + f.z * q2.z + f.w * q2.w;
#pragma unroll
                for (int o = 8; o > 0; o >>= 1) {
                    d0 += __shfl_xor_sync(0xFFFFFFFFu, d0, o);
                    d1 += __shfl_xor_sync(0xFFFFFFFFu, d1, o);
                    d2 += __shfl_xor_sync(0xFFFFFFFFu, d2, o);
                }
                if (ll == 0) {
                    g_S1[b * F_SZ + i] = d1;
                    g_SA[b * F_SZ + i] = d0 * d2;
                }
            }
        }
    }
}

// ---------------- K3: persistent mma.sync main kernel, 512 threads ----------------
// 16 warps: pair p = w&7 owns tile (m0=(p>>1)*32, n0=(p&1)*32); khalf = w>>3
// splits K=256 into two halves of 8 k-iters. Partials combined via smem staging
// (reuses Z-lo region after mainloop), low warp does the epilogue.
__global__ void __launch_bounds__(512, 1)
k_main(float* __restrict__ out) {
    extern __shared__ char sm[];
    uint32_t sb = smem_u32(sm);
    int tid = threadIdx.x, w = tid >> 5, lane = tid & 31;
    int c = blockIdx.x;
    int u0 = (c * NUNITS) / GRID_MAIN, u1 = ((c + 1) * NUNITS) / GRID_MAIN;

    int p = w & 7, khalf = w >> 3;
    int m0 = (p >> 1) * 32;
    int n0 = (p & 1) * 32;
    int g = lane >> 2, t4 = lane & 3;

    uint32_t aBase = sb + SM_AHI + (uint32_t)(m0 + (lane & 15)) * (A_STR * 2)
                     + (uint32_t)(lane >> 4) * 16;
    uint32_t bBase = sb + SM_ZH + (uint32_t)(lane & 15) * (Z_STR * 2)
                     + (uint32_t)(n0 + 8 * (lane >> 4)) * 2;
    // staging (reuse Z-lo region): pair p, lane l -> 32 floats
    float* stage = (float*)(sm + SM_ZL) + p * 1024 + lane * 32;

    int curH = -1;
    for (int u = u0; u < u1; u++) {
        int h = u >> 10, b = u & 1023;

        if (h != curH) {
            __syncthreads();
            const uint2* mh = (const uint2*)(g_Mhi + h * 128 * F_SZ);
            const uint2* ml = (const uint2*)(g_Mlo + h * 128 * F_SZ);
            for (int idx = tid; idx < 128 * 64; idx += 512) {
                int r = idx >> 6, c4 = idx & 63;
                *(uint2*)(sm + SM_AHI + r * (A_STR * 2) + c4 * 8) = mh[idx];
                *(uint2*)(sm + SM_ALO + r * (A_STR * 2) + c4 * 8) = ml[idx];
            }
            curH = h;
        }

        __syncthreads();   // prior staging/Z readers done
        // ---- build Z[j][d] = S1[b,j]*Q2[j,d], bf16 hi/lo ----
        {
            const float* q2 = g_qkv + 2 * F_SZ * D_SZ;
            const float* s1p = g_S1 + b * F_SZ;
            for (int e = tid; e < 256 * 32; e += 512) {
                int j = e >> 5, dp = e & 31;
                float s1 = __ldg(s1p + j);
                float2 q = ((const float2*)(q2 + j * 64))[dp];
                float z0 = q.x * s1, z1 = q.y * s1;
                __nv_bfloat16 h0 = __float2bfloat16(z0);
                __nv_bfloat16 h1 = __float2bfloat16(z1);
                __nv_bfloat16 l0 = __float2bfloat16(z0 - __bfloat162float(h0));
                __nv_bfloat16 l1 = __float2bfloat16(z1 - __bfloat162float(h1));
                uint32_t hp = ((uint32_t)__bfloat16_as_ushort(h1) << 16) |
                              __bfloat16_as_ushort(h0);
                uint32_t lp = ((uint32_t)__bfloat16_as_ushort(l1) << 16) |
                              __bfloat16_as_ushort(l0);
                *(uint32_t*)(sm + SM_ZH + j * (Z_STR * 2) + dp * 4) = hp;
                *(uint32_t*)(sm + SM_ZL + j * (Z_STR * 2) + dp * 4) = lp;
            }
        }
        __syncthreads();

        // ---- mma mainloop: warp tile 32x32, this warp's K-half (8 k-iters) ----
        float acc[8][4];
#pragma unroll
        for (int i = 0; i < 8; i++)
#pragma unroll
            for (int q = 0; q < 4; q++) acc[i][q] = 0.f;

#pragma unroll 2
        for (int kk = 0; kk < 8; kk++) {
            int k = khalf * 8 + kk;
            uint32_t kA = (uint32_t)k * 32;
            uint32_t kB = (uint32_t)k * 16 * (Z_STR * 2);
            uint32_t ah0[4], ah1[4], al0[4], al1[4];
            LDSM4(ah0, aBase + kA);
            LDSM4(ah1, aBase + 16 * (A_STR * 2) + kA);
            LDSM4(al0, aBase + (SM_ALO - SM_AHI) + kA);
            LDSM4(al1, aBase + (SM_ALO - SM_AHI) + 16 * (A_STR * 2) + kA);
            uint32_t bh0[4], bh1[4], bl0[4], bl1[4];
            LDSM4T(bh0, bBase + kB);
            LDSM4T(bh1, bBase + kB + 32);
            LDSM4T(bl0, bBase + (SM_ZL - SM_ZH) + kB);
            LDSM4T(bl1, bBase + (SM_ZL - SM_ZH) + kB + 32);

            MMA16816(acc[0], ah0, bh0[0], bh0[1]);
            MMA16816(acc[1], ah0, bh0[2], bh0[3]);
            MMA16816(acc[2], ah0, bh1[0], bh1[1]);
            MMA16816(acc[3], ah0, bh1[2], bh1[3]);
            MMA16816(acc[4], ah1, bh0[0], bh0[1]);
            MMA16816(acc[5], ah1, bh0[2], bh0[3]);
            MMA16816(acc[6], ah1, bh1[0], bh1[1]);
            MMA16816(acc[7], ah1, bh1[2], bh1[3]);

            MMA16816(acc[0], ah0, bl0[0], bl0[1]);
            MMA16816(acc[1], ah0, bl0[2], bl0[3]);
            MMA16816(acc[2], ah0, bl1[0], bl1[1]);
            MMA16816(acc[3], ah0, bl1[2], bl1[3]);
            MMA16816(acc[4], ah1, bl0[0], bl0[1]);
            MMA16816(acc[5], ah1, bl0[2], bl0[3]);
            MMA16816(acc[6], ah1, bl1[0], bl1[1]);
            MMA16816(acc[7], ah1, bl1[2], bl1[3]);

            MMA16816(acc[0], al0, bh0[0], bh0[1]);
            MMA16816(acc[1], al0, bh0[2], bh0[3]);
            MMA16816(acc[2], al0, bh1[0], bh1[1]);
            MMA16816(acc[3], al0, bh1[2], bh1[3]);
            MMA16816(acc[4], al1, bh0[0], bh0[1]);
            MMA16816(acc[5], al1, bh0[2], bh0[3]);
            MMA16816(acc[6], al1, bh1[0], bh1[1]);
            MMA16816(acc[7], al1, bh1[2], bh1[3]);
        }
        __syncthreads();   // mainloop done (Z-lo free for staging)

        if (khalf == 1) {
            // high warp: dump partials to staging
            float4* st = (float4*)stage;
#pragma unroll
            for (int i = 0; i < 8; i++)
                st[i] = make_float4(acc[i][0], acc[i][1], acc[i][2], acc[i][3]);
        }
        __syncthreads();

        if (khalf == 0) {
            // low warp: combine + scale by SA + store
            const float4* st = (const float4*)stage;
#pragma unroll
            for (int i = 0; i < 8; i++) {
                float4 v = st[i];
                acc[i][0] += v.x; acc[i][1] += v.y;
                acc[i][2] += v.z; acc[i][3] += v.w;
            }
            const float* sap = g_SA + b * F_SZ + h * 128;
            float* ob = out + (size_t)b * (F_SZ * D_SZ) + h * 128 * D_SZ;
#pragma unroll
            for (int mt = 0; mt < 2; mt++) {
                int r0 = m0 + mt * 16 + g;
                float sa0 = __ldg(sap + r0), sa1 = __ldg(sap + r0 + 8);
#pragma unroll
                for (int pt = 0; pt < 4; pt++) {
                    float* a = acc[mt * 4 + pt];
                    int col = n0 + pt * 8 + 2 * t4;
                    *(float2*)(ob + r0 * 64 + col) =
                        make_float2(a[0] * sa0, a[1] * sa0);
                    *(float2*)(ob + (r0 + 8) * 64 + col) =
                        make_float2(a[2] * sa1, a[3] * sa1);
                }
            }
        }
    }
}

// ---------------- launch ----------------
extern "C" void kernel_launch(void* const* d_in, const int* in_sizes, int n_in,
                              void* d_out, int out_size) {
    const float *feature = nullptr, *indicator = nullptr;
    const float *Wqk = nullptr, *Wqkv = nullptr;
    for (int k = 0; k < n_in; k++) {
        switch (in_sizes[k]) {
            case B_SZ * F_SZ * D_SZ: feature   = (const float*)d_in[k]; break;
            case F_SZ * D_SZ:        indicator = (const float*)d_in[k]; break;
            case 2 * D_SZ * D_SZ:    Wqk       = (const float*)d_in[k]; break;
            case 3 * D_SZ * D_SZ:    Wqkv      = (const float*)d_in[k]; break;
        }
    }
    float* out = (float*)d_out;

    cudaFuncSetAttribute(k_main, cudaFuncAttributeMaxDynamicSharedMemorySize,
                         SMEM_TOTAL);

    k_qkv<<<dim3(64, 5), 256>>>(indicator, Wqk, Wqkv);
    k_prep<<<512, 256>>>(feature);
    k_main<<<GRID_MAIN, 512, SMEM_TOTAL>>>(out);
}